// round 9
// baseline (speedup 1.0000x reference)
#include <cuda_runtime.h>
#include <cuda_bf16.h>
#include <cstdint>

// Problem dims
#define VOCAB 8192
#define HID   1024
#define BATCH 64
#define SEQ   256

// -------- device scratch (static: no runtime allocation allowed) --------
__device__ float g_whhT[HID * HID];                 // w_hh transposed: [j][k]
__device__ float g_H[(size_t)SEQ * BATCH * HID];    // all hidden states [t][b][h]
__device__ float g_h[2][BATCH * HID];               // ping-pong hidden state

// ---------------------------------------------------------------
// Transpose w_hh (1024x1024) -> g_whhT so the step kernel reads
// contiguous rows for each output column.
// ---------------------------------------------------------------
__global__ void k_transpose(const float* __restrict__ w) {
    __shared__ float tile[32][33];
    int bx = blockIdx.x * 32, by = blockIdx.y * 32;
    int tx = threadIdx.x, ty = threadIdx.y;
    #pragma unroll
    for (int i = 0; i < 32; i += 8)
        tile[ty + i][tx] = w[(by + ty + i) * HID + bx + tx];
    __syncthreads();
    #pragma unroll
    for (int i = 0; i < 32; i += 8)
        g_whhT[(bx + ty + i) * HID + by + tx] = tile[tx][ty + i];
}

__global__ void k_init(const float* __restrict__ status) {
    int i = blockIdx.x * blockDim.x + threadIdx.x;
    if (i < BATCH * HID) g_h[0][i] = status[i];
}

// ---------------------------------------------------------------
// One recurrence step: h_out = tanh(h_in @ w_hh + w_xh[X[:,t]] + b_h)
// grid: (64 j-chunks of 16, 2 b-halves of 32), 256 threads.
// Block tile: 32 b x 16 j. Thread: tj = tid&15, tb = tid>>4,
// computes (b = bbase+tb, j) and (b = bbase+tb+16, j).
// ---------------------------------------------------------------
__global__ __launch_bounds__(256) void k_step(
    const float* __restrict__ w_xh, const int* __restrict__ X,
    const float* __restrict__ b_h, int t, int par)
{
    const int jbase = blockIdx.x * 16;
    const int bbase = blockIdx.y * 32;
    const float* __restrict__ hin = g_h[par];
    float* __restrict__ hout = g_h[par ^ 1];

    __shared__ float sh[32][129];   // h tile
    __shared__ float sw[16][129];   // w_hhT tile

    const int tid = threadIdx.x;
    const int tj = tid & 15;
    const int tb = tid >> 4;

    float acc0 = 0.f, acc1 = 0.f;

    for (int k0 = 0; k0 < HID; k0 += 128) {
        // stage h tile: 32 rows x 128
        for (int i = tid; i < 32 * 128; i += 256) {
            int r = i >> 7, c = i & 127;
            sh[r][c] = hin[(bbase + r) * HID + k0 + c];
        }
        // stage w tile: 16 rows x 128
        for (int i = tid; i < 16 * 128; i += 256) {
            int r = i >> 7, c = i & 127;
            sw[r][c] = g_whhT[(jbase + r) * HID + k0 + c];
        }
        __syncthreads();
        #pragma unroll 8
        for (int k = 0; k < 128; k++) {
            float wv = sw[tj][k];
            acc0 += sh[tb][k] * wv;
            acc1 += sh[tb + 16][k] * wv;
        }
        __syncthreads();
    }

    const int j = jbase + tj;
    const float bh = b_h[j];
    {
        int b = bbase + tb;
        int xi = X[b * SEQ + t];
        float v = tanhf(acc0 + w_xh[(size_t)xi * HID + j] + bh);
        hout[b * HID + j] = v;
        g_H[((size_t)t * BATCH + b) * HID + j] = v;
    }
    {
        int b = bbase + tb + 16;
        int xi = X[b * SEQ + t];
        float v = tanhf(acc1 + w_xh[(size_t)xi * HID + j] + bh);
        hout[b * HID + j] = v;
        g_H[((size_t)t * BATCH + b) * HID + j] = v;
    }
}

// ---------------------------------------------------------------
// Big output GEMM with tf32 mma.sync:
//   Y[m, n] = sum_k H[m,k] * w_ho[k,n] + b_o[n]
// M = 16384, K = 1024, N = 8192, fp32 accumulate.
// Block tile 128x128, BK=32, 8 warps (4x2), warp tile 32x64.
// ---------------------------------------------------------------
__device__ __forceinline__ uint32_t f2tf32(float x) {
    uint32_t r;
    asm("cvt.rna.tf32.f32 %0, %1;" : "=r"(r) : "f"(x));
    return r;
}

__device__ __forceinline__ void mma_16n8k8(float* c, const uint32_t* a, const uint32_t* b) {
    asm volatile(
        "mma.sync.aligned.m16n8k8.row.col.f32.tf32.tf32.f32 "
        "{%0,%1,%2,%3}, {%4,%5,%6,%7}, {%8,%9}, {%0,%1,%2,%3};\n"
        : "+f"(c[0]), "+f"(c[1]), "+f"(c[2]), "+f"(c[3])
        : "r"(a[0]), "r"(a[1]), "r"(a[2]), "r"(a[3]), "r"(b[0]), "r"(b[1]));
}

__global__ __launch_bounds__(256) void k_gemm(
    const float* __restrict__ Wo, const float* __restrict__ b_o,
    float* __restrict__ Y)
{
    __shared__ float As[128][36];   // [m][k]
    __shared__ float Bs[128][36];   // [n][k]  (transposed tile of w_ho)

    const int m0 = blockIdx.y * 128;
    const int n0 = blockIdx.x * 128;
    const int tid = threadIdx.x;
    const int warp = tid >> 5, lane = tid & 31;
    const int wr = warp >> 1;       // 0..3  (m direction, 32 rows each)
    const int wc = warp & 1;        // 0..1  (n direction, 64 cols each)
    const int g = lane >> 2;        // groupID
    const int tg = lane & 3;        // thread in group

    float c[2][8][4];
    #pragma unroll
    for (int i = 0; i < 2; i++)
        #pragma unroll
        for (int jn = 0; jn < 8; jn++)
            #pragma unroll
            for (int q = 0; q < 4; q++) c[i][jn][q] = 0.f;

    for (int kt = 0; kt < HID; kt += 32) {
        // load A tile: 128 rows x 32 k (float4 along k)
        #pragma unroll
        for (int r = 0; r < 4; r++) {
            int i = tid + r * 256;           // 0..1023
            int row = i >> 3;
            int c4 = (i & 7) << 2;
            float4 v = *reinterpret_cast<const float4*>(
                &g_H[((size_t)(m0 + row)) * HID + kt + c4]);
            As[row][c4 + 0] = v.x; As[row][c4 + 1] = v.y;
            As[row][c4 + 2] = v.z; As[row][c4 + 3] = v.w;
        }
        // load B tile: 32 k x 128 n (float4 along n), store transposed
        #pragma unroll
        for (int r = 0; r < 4; r++) {
            int i = tid + r * 256;
            int k = i >> 5;                  // 0..31
            int n4 = (i & 31) << 2;          // 0..124
            float4 v = *reinterpret_cast<const float4*>(
                &Wo[((size_t)(kt + k)) * VOCAB + n0 + n4]);
            Bs[n4 + 0][k] = v.x; Bs[n4 + 1][k] = v.y;
            Bs[n4 + 2][k] = v.z; Bs[n4 + 3][k] = v.w;
        }
        __syncthreads();

        #pragma unroll
        for (int kk = 0; kk < 4; kk++) {
            uint32_t a[2][4];
            #pragma unroll
            for (int im = 0; im < 2; im++) {
                int row = wr * 32 + im * 16;
                a[im][0] = f2tf32(As[row + g][kk * 8 + tg]);
                a[im][1] = f2tf32(As[row + g + 8][kk * 8 + tg]);
                a[im][2] = f2tf32(As[row + g][kk * 8 + tg + 4]);
                a[im][3] = f2tf32(As[row + g + 8][kk * 8 + tg + 4]);
            }
            uint32_t b[8][2];
            #pragma unroll
            for (int in = 0; in < 8; in++) {
                int n = wc * 64 + in * 8 + g;
                b[in][0] = f2tf32(Bs[n][kk * 8 + tg]);
                b[in][1] = f2tf32(Bs[n][kk * 8 + tg + 4]);
            }
            #pragma unroll
            for (int im = 0; im < 2; im++)
                #pragma unroll
                for (int in = 0; in < 8; in++)
                    mma_16n8k8(c[im][in], a[im], b[in]);
        }
        __syncthreads();
    }

    // epilogue: add bias, write fp32 Y
    #pragma unroll
    for (int im = 0; im < 2; im++) {
        #pragma unroll
        for (int in = 0; in < 8; in++) {
            int col = n0 + wc * 64 + in * 8 + tg * 2;
            float bo0 = b_o[col], bo1 = b_o[col + 1];
            int row0 = m0 + wr * 32 + im * 16 + g;
            float2 v0 = make_float2(c[im][in][0] + bo0, c[im][in][1] + bo1);
            float2 v1 = make_float2(c[im][in][2] + bo0, c[im][in][3] + bo1);
            *reinterpret_cast<float2*>(&Y[(size_t)row0 * VOCAB + col]) = v0;
            *reinterpret_cast<float2*>(&Y[((size_t)row0 + 8) * VOCAB + col]) = v1;
        }
    }
}

__global__ void k_copy_hfinal(float* __restrict__ dst) {
    int i = blockIdx.x * blockDim.x + threadIdx.x;
    if (i < BATCH * HID) dst[i] = g_h[0][i];   // after 256 steps, final state is in parity 0
}

// ---------------------------------------------------------------
extern "C" void kernel_launch(void* const* d_in, const int* in_sizes, int n_in,
                              void* d_out, int out_size) {
    const int*   X      = (const int*)d_in[0];    // (B, S) int32
    const float* status = (const float*)d_in[1];  // (B, H)
    const float* w_xh   = (const float*)d_in[2];  // (V, H)
    const float* w_hh   = (const float*)d_in[3];  // (H, H)
    const float* w_ho   = (const float*)d_in[4];  // (H, V)
    const float* b_h    = (const float*)d_in[5];  // (H)
    const float* b_o    = (const float*)d_in[6];  // (V)
    float* out = (float*)d_out;

    k_transpose<<<dim3(32, 32), dim3(32, 8)>>>(w_hh);
    k_init<<<(BATCH * HID + 255) / 256, 256>>>(status);

    for (int t = 0; t < SEQ; t++)
        k_step<<<dim3(64, 2), 256>>>(w_xh, X, b_h, t, t & 1);

    // Y: (S*B, V) = (16384, 8192)
    k_gemm<<<dim3(VOCAB / 128, (SEQ * BATCH) / 128), 256>>>(w_ho, b_o, out);

    // h_final appended after Y if the output buffer expects it
    long long ybytes = (long long)SEQ * BATCH * VOCAB;
    if ((long long)out_size >= ybytes + (long long)BATCH * HID)
        k_copy_hfinal<<<(BATCH * HID + 255) / 256, 256>>>(out + (size_t)SEQ * BATCH * VOCAB);
}

// round 10
// speedup vs baseline: 1.2521x; 1.2521x over previous
#include <cuda_runtime.h>
#include <cuda_bf16.h>
#include <cstdint>

// Problem dims
#define VOCAB 8192
#define HID   1024
#define BATCH 64
#define SEQ   256

#define NBLK  128      // persistent blocks (<=148 SMs -> co-resident)
#define JPB   8        // j columns per block (128*8 = 1024)

// -------- device scratch (static: no runtime allocation allowed) --------
__device__ __align__(16) float g_H[(size_t)SEQ * BATCH * HID];  // all hidden states [t][b][h]
__device__ __align__(16) float g_h[2][BATCH * HID];             // ping-pong hidden state
__device__ unsigned g_cnt;   // grid barrier arrive counter
__device__ unsigned g_gen;   // grid barrier generation

__global__ void k_init(const float* __restrict__ status) {
    int i = blockIdx.x * blockDim.x + threadIdx.x;
    if (i < BATCH * HID) g_h[0][i] = status[i];
    if (i == 0) { g_cnt = 0; g_gen = 0; }
}

// packed dual fp32 FMA (sm_100+): acc = a*b + acc elementwise on f32x2
__device__ __forceinline__ void ffma2(unsigned long long& acc,
                                      unsigned long long a, unsigned long long b) {
    asm("fma.rn.f32x2 %0, %1, %2, %0;" : "+l"(acc) : "l"(a), "l"(b));
}

__device__ __forceinline__ void ldg_chunk(const float* __restrict__ hin,
                                          int sb, int seg, int c, float4* pf) {
    #pragma unroll
    for (int i = 0; i < 8; i++)
        pf[i] = __ldcg((const float4*)&hin[(size_t)sb * HID + c * 128 + seg * 32 + i * 4]);
}

__device__ __forceinline__ void sts_chunk(float* buf, int sb, int seg, const float4* pf) {
    #pragma unroll
    for (int i = 0; i < 8; i++) {
        int kl = seg * 32 + i * 4;
        buf[(kl + 0) * 68 + sb] = pf[i].x;   // warp spans 32 consecutive sb -> conflict-free
        buf[(kl + 1) * 68 + sb] = pf[i].y;
        buf[(kl + 2) * 68 + sb] = pf[i].z;
        buf[(kl + 3) * 68 + sb] = pf[i].w;
    }
}

// ---------------------------------------------------------------
// Persistent RNN recurrence: all 256 steps in one kernel.
// Block b owns j-slice [b*8, b*8+8) of w_hh (kept in smem for the
// whole kernel). Per step: stage h (L2, ld.cg) in double-buffered
// 128-k chunks, split-k over 8 warps, smem-reduce, epilogue, grid
// barrier.
// dyn smem: wsT 32KB + 2 x 34KB h-chunk buffers (red aliases buf0)
// ---------------------------------------------------------------
__global__ __launch_bounds__(256, 1) void k_rnn(
    const int* __restrict__ X, const float* __restrict__ w_xh,
    const float* __restrict__ w_hh, const float* __restrict__ b_h)
{
    extern __shared__ float smem[];
    float* wsT  = smem;                    // [1024][8]  w_hh[k][jbase+j]
    float* buf0 = smem + 8192;             // [128][68]  h chunk (transposed: [k][b])
    float* buf1 = smem + 8192 + 8704;
    float* red  = buf0;                    // [8][520] partials, aliased (used after chunks)

    const int tid  = threadIdx.x;
    const int warp = tid >> 5;
    const int lane = tid & 31;
    const int bg   = lane & 7;             // batch-group (8 batches each)
    const int jg   = lane >> 3;            // j-group (2 j each)
    const int jbase = blockIdx.x * JPB;

    // ---- stage w slice once (entire kernel lifetime) ----
    #pragma unroll
    for (int kk = 0; kk < 4; kk++) {
        int k = tid * 4 + kk;
        float4 a = __ldg((const float4*)&w_hh[(size_t)k * HID + jbase]);
        float4 b = __ldg((const float4*)&w_hh[(size_t)k * HID + jbase + 4]);
        *(float4*)&wsT[k * 8]     = a;
        *(float4*)&wsT[k * 8 + 4] = b;
    }

    // epilogue constants (thread handles output pair o, o+1: same j, batches eb, eb+1)
    const int o  = 2 * tid;
    const int eb = o & 63;
    const int ej = o >> 6;
    const float bh = b_h[jbase + ej];

    // staging constants
    const int sb  = tid & 63;
    const int seg = tid >> 6;

    __syncthreads();

    for (int t = 0; t < SEQ; t++) {
        const int par = t & 1;
        const float* __restrict__ hin  = g_h[par];
        float* __restrict__ hout = g_h[par ^ 1];

        unsigned long long acc[8];         // 4 b-pairs x 2 j, packed f32x2
        #pragma unroll
        for (int i = 0; i < 8; i++) acc[i] = 0ull;

        // prologue: chunk 0
        float4 pf[8];
        ldg_chunk(hin, sb, seg, 0, pf);
        sts_chunk(buf0, sb, seg, pf);
        __syncthreads();

        #pragma unroll 1
        for (int c = 0; c < 8; c++) {
            float* cur = (c & 1) ? buf1 : buf0;
            if (c < 7) ldg_chunk(hin, sb, seg, c + 1, pf);   // prefetch (L2 latency hidden by compute)

            // compute: warp owns 16 k rows of this chunk
            const float* hrow = cur + (warp * 16) * 68 + bg * 8;
            const float* wrow = wsT + ((size_t)(c * 128 + warp * 16)) * 8 + jg * 2;
            #pragma unroll
            for (int kk = 0; kk < 16; kk++) {
                ulonglong2 h01 = *(const ulonglong2*)(hrow + kk * 68);      // b-pairs (b0,b1),(b2,b3)
                ulonglong2 h23 = *(const ulonglong2*)(hrow + kk * 68 + 4);  // (b4,b5),(b6,b7)
                float2 wv = *(const float2*)(wrow + kk * 8);
                unsigned long long w0d, w1d;
                asm("mov.b64 %0, {%1, %1};" : "=l"(w0d) : "f"(wv.x));
                asm("mov.b64 %0, {%1, %1};" : "=l"(w1d) : "f"(wv.y));
                ffma2(acc[0], h01.x, w0d); ffma2(acc[1], h01.y, w0d);
                ffma2(acc[2], h23.x, w0d); ffma2(acc[3], h23.y, w0d);
                ffma2(acc[4], h01.x, w1d); ffma2(acc[5], h01.y, w1d);
                ffma2(acc[6], h23.x, w1d); ffma2(acc[7], h23.y, w1d);
            }
            __syncthreads();
            if (c < 7) {
                sts_chunk((c & 1) ? buf0 : buf1, sb, seg, pf);
                __syncthreads();
            }
        }

        // split-k reduction: each warp dumps its 16 partials (as b-pairs)
        #pragma unroll
        for (int jj = 0; jj < 2; jj++)
            #pragma unroll
            for (int p = 0; p < 4; p++) {
                int oo = (jg * 2 + jj) * 64 + bg * 8 + 2 * p;   // o = j*64 + b (b even)
                *(unsigned long long*)&red[warp * 520 + oo] = acc[jj * 4 + p];
            }
        __syncthreads();

        // final sum + epilogue: thread -> outputs (eb, ej), (eb+1, ej)
        float2 s = make_float2(0.f, 0.f);
        #pragma unroll
        for (int w = 0; w < 8; w++) {
            float2 v = *(const float2*)&red[w * 520 + o];
            s.x += v.x; s.y += v.y;
        }
        int xi0 = X[eb * SEQ + t];
        int xi1 = X[(eb + 1) * SEQ + t];
        float e0 = __ldg(&w_xh[(size_t)xi0 * HID + jbase + ej]);
        float e1 = __ldg(&w_xh[(size_t)xi1 * HID + jbase + ej]);
        float v0 = tanhf(s.x + e0 + bh);
        float v1 = tanhf(s.y + e1 + bh);
        __stcg(&hout[eb * HID + jbase + ej], v0);          // L2-coherent for cross-SM reads
        __stcg(&hout[(eb + 1) * HID + jbase + ej], v1);
        g_H[((size_t)t * BATCH + eb) * HID + jbase + ej] = v0;
        g_H[((size_t)t * BATCH + eb + 1) * HID + jbase + ej] = v1;

        // grid barrier (sense via generation counter); skip after last step
        if (t < SEQ - 1) {
            __syncthreads();
            if (tid == 0) {
                __threadfence();
                unsigned prev = atomicAdd(&g_cnt, 1);
                if (prev == NBLK - 1) {
                    g_cnt = 0;
                    __threadfence();
                    atomicAdd(&g_gen, 1);   // release
                } else {
                    unsigned target = (unsigned)(t + 1), v;
                    do {
                        __nanosleep(32);
                        asm volatile("ld.acquire.gpu.global.u32 %0, [%1];"
                                     : "=r"(v) : "l"(&g_gen) : "memory");
                    } while (v < target);
                }
            }
            __syncthreads();
        } else {
            __syncthreads();   // protect red (aliased smem) until all threads read it
        }
    }
}

// ---------------------------------------------------------------
// Big output GEMM with tf32 mma.sync:
//   Y[m, n] = sum_k H[m,k] * w_ho[k,n] + b_o[n]
// M = 16384, K = 1024, N = 8192, fp32 accumulate.
// Block tile 128x128, BK=32, 8 warps (4x2), warp tile 32x64.
// ---------------------------------------------------------------
__device__ __forceinline__ uint32_t f2tf32(float x) {
    uint32_t r;
    asm("cvt.rna.tf32.f32 %0, %1;" : "=r"(r) : "f"(x));
    return r;
}

__device__ __forceinline__ void mma_16n8k8(float* c, const uint32_t* a, const uint32_t* b) {
    asm volatile(
        "mma.sync.aligned.m16n8k8.row.col.f32.tf32.tf32.f32 "
        "{%0,%1,%2,%3}, {%4,%5,%6,%7}, {%8,%9}, {%0,%1,%2,%3};\n"
        : "+f"(c[0]), "+f"(c[1]), "+f"(c[2]), "+f"(c[3])
        : "r"(a[0]), "r"(a[1]), "r"(a[2]), "r"(a[3]), "r"(b[0]), "r"(b[1]));
}

__global__ __launch_bounds__(256) void k_gemm(
    const float* __restrict__ Wo, const float* __restrict__ b_o,
    float* __restrict__ Y)
{
    __shared__ float As[128][36];   // [m][k]
    __shared__ float Bs[128][36];   // [n][k]  (transposed tile of w_ho)

    const int m0 = blockIdx.y * 128;
    const int n0 = blockIdx.x * 128;
    const int tid = threadIdx.x;
    const int warp = tid >> 5, lane = tid & 31;
    const int wr = warp >> 1;       // 0..3  (m direction, 32 rows each)
    const int wc = warp & 1;        // 0..1  (n direction, 64 cols each)
    const int g = lane >> 2;        // groupID
    const int tg = lane & 3;        // thread in group

    float c[2][8][4];
    #pragma unroll
    for (int i = 0; i < 2; i++)
        #pragma unroll
        for (int jn = 0; jn < 8; jn++)
            #pragma unroll
            for (int q = 0; q < 4; q++) c[i][jn][q] = 0.f;

    for (int kt = 0; kt < HID; kt += 32) {
        // load A tile: 128 rows x 32 k (float4 along k)
        #pragma unroll
        for (int r = 0; r < 4; r++) {
            int i = tid + r * 256;           // 0..1023
            int row = i >> 3;
            int c4 = (i & 7) << 2;
            float4 v = *reinterpret_cast<const float4*>(
                &g_H[((size_t)(m0 + row)) * HID + kt + c4]);
            As[row][c4 + 0] = v.x; As[row][c4 + 1] = v.y;
            As[row][c4 + 2] = v.z; As[row][c4 + 3] = v.w;
        }
        // load B tile: 32 k x 128 n (float4 along n), store transposed
        #pragma unroll
        for (int r = 0; r < 4; r++) {
            int i = tid + r * 256;
            int k = i >> 5;                  // 0..31
            int n4 = (i & 31) << 2;          // 0..124
            float4 v = *reinterpret_cast<const float4*>(
                &Wo[((size_t)(kt + k)) * VOCAB + n0 + n4]);
            Bs[n4 + 0][k] = v.x; Bs[n4 + 1][k] = v.y;
            Bs[n4 + 2][k] = v.z; Bs[n4 + 3][k] = v.w;
        }
        __syncthreads();

        #pragma unroll
        for (int kk = 0; kk < 4; kk++) {
            uint32_t a[2][4];
            #pragma unroll
            for (int im = 0; im < 2; im++) {
                int row = wr * 32 + im * 16;
                a[im][0] = f2tf32(As[row + g][kk * 8 + tg]);
                a[im][1] = f2tf32(As[row + g + 8][kk * 8 + tg]);
                a[im][2] = f2tf32(As[row + g][kk * 8 + tg + 4]);
                a[im][3] = f2tf32(As[row + g + 8][kk * 8 + tg + 4]);
            }
            uint32_t b[8][2];
            #pragma unroll
            for (int in = 0; in < 8; in++) {
                int n = wc * 64 + in * 8 + g;
                b[in][0] = f2tf32(Bs[n][kk * 8 + tg]);
                b[in][1] = f2tf32(Bs[n][kk * 8 + tg + 4]);
            }
            #pragma unroll
            for (int im = 0; im < 2; im++)
                #pragma unroll
                for (int in = 0; in < 8; in++)
                    mma_16n8k8(c[im][in], a[im], b[in]);
        }
        __syncthreads();
    }

    // epilogue: add bias, write fp32 Y
    #pragma unroll
    for (int im = 0; im < 2; im++) {
        #pragma unroll
        for (int in = 0; in < 8; in++) {
            int col = n0 + wc * 64 + in * 8 + tg * 2;
            float bo0 = b_o[col], bo1 = b_o[col + 1];
            int row0 = m0 + wr * 32 + im * 16 + g;
            float2 v0 = make_float2(c[im][in][0] + bo0, c[im][in][1] + bo1);
            float2 v1 = make_float2(c[im][in][2] + bo0, c[im][in][3] + bo1);
            *reinterpret_cast<float2*>(&Y[(size_t)row0 * VOCAB + col]) = v0;
            *reinterpret_cast<float2*>(&Y[((size_t)row0 + 8) * VOCAB + col]) = v1;
        }
    }
}

__global__ void k_copy_hfinal(float* __restrict__ dst) {
    int i = blockIdx.x * blockDim.x + threadIdx.x;
    if (i < BATCH * HID) dst[i] = g_h[0][i];   // after 256 steps, final state is in parity 0
}

// ---------------------------------------------------------------
extern "C" void kernel_launch(void* const* d_in, const int* in_sizes, int n_in,
                              void* d_out, int out_size) {
    const int*   X      = (const int*)d_in[0];    // (B, S) int32
    const float* status = (const float*)d_in[1];  // (B, H)
    const float* w_xh   = (const float*)d_in[2];  // (V, H)
    const float* w_hh   = (const float*)d_in[3];  // (H, H)
    const float* w_ho   = (const float*)d_in[4];  // (H, V)
    const float* b_h    = (const float*)d_in[5];  // (H)
    const float* b_o    = (const float*)d_in[6];  // (V)
    float* out = (float*)d_out;

    const int smem_bytes = (8192 + 2 * 8704) * 4;   // 102400 B
    cudaFuncSetAttribute(k_rnn, cudaFuncAttributeMaxDynamicSharedMemorySize, smem_bytes);

    k_init<<<(BATCH * HID + 255) / 256, 256>>>(status);

    // all 256 recurrence steps in one persistent kernel
    k_rnn<<<NBLK, 256, smem_bytes>>>(X, w_xh, w_hh, b_h);

    // Y: (S*B, V) = (16384, 8192)
    k_gemm<<<dim3(VOCAB / 128, (SEQ * BATCH) / 128), 256>>>(w_ho, b_o, out);

    // h_final appended after Y if the output buffer expects it
    long long ybytes = (long long)SEQ * BATCH * VOCAB;
    if ((long long)out_size >= ybytes + (long long)BATCH * HID)
        k_copy_hfinal<<<(BATCH * HID + 255) / 256, 256>>>(out + (size_t)SEQ * BATCH * VOCAB);
}

// round 13
// speedup vs baseline: 2.0545x; 1.6409x over previous
#include <cuda_runtime.h>
#include <cuda_bf16.h>
#include <cstdint>

// Problem dims
#define VOCAB 8192
#define HID   1024
#define BATCH 64
#define SEQ   256

#define NBLK  128      // persistent blocks (1 per SM, <=148 -> co-resident)
#define JPB   8        // j columns per block (128*8 = 1024)

typedef unsigned long long ull;

// -------- device scratch (static: no runtime allocation allowed) --------
__device__ __align__(16) float g_H[(size_t)SEQ * BATCH * HID];  // all hidden states [t][b][h]
__device__ __align__(16) float g_h[2][BATCH * HID];             // ping-pong hidden state
__device__ unsigned g_cnt;   // grid barrier arrive counter
__device__ unsigned g_gen;   // grid barrier generation

__global__ void k_init(const float* __restrict__ status) {
    int i = blockIdx.x * blockDim.x + threadIdx.x;
    if (i < BATCH * HID) g_h[0][i] = status[i];
    if (i == 0) { g_cnt = 0; g_gen = 0; }
}

// packed dual fp32 FMA (sm_100+): acc = a*b + acc elementwise on f32x2
__device__ __forceinline__ void ffma2(ull& acc, ull a, ull b) {
    asm("fma.rn.f32x2 %0, %1, %2, %0;" : "+l"(acc) : "l"(a), "l"(b));
}

// ---------------------------------------------------------------
// Persistent RNN recurrence: all 256 steps in one kernel.
// Block owns j-slice [blockIdx*8, +8) of w_hh (smem-resident, tf
// layout [j][1026]). Per step: stage h (coalesced ld.cg, float4,
// XOR-swizzled smem), split-k over 8 warps with f32x2 k-pair
// packing, smem reduce, epilogue (gather+bias+tanh), grid barrier.
// dyn smem: wsT 8*1026 + 2 h-chunk bufs 64*128 (red aliases buf0)
// ---------------------------------------------------------------
__global__ __launch_bounds__(256, 1) void k_rnn(
    const int* __restrict__ X, const float* __restrict__ w_xh,
    const float* __restrict__ w_hh, const float* __restrict__ b_h)
{
    extern __shared__ float smem[];
    float* wsT  = smem;                    // [8][1026]  w_hh[jbase+j][k]
    float* buf0 = smem + 8 * 1026;         // [64][128]  h chunk, float4-XOR swizzled
    float* buf1 = buf0 + 64 * 128;
    ull*   red  = (ull*)buf0;              // [8][512] f32x2 partials, aliased

    const int tid  = threadIdx.x;
    const int warp = tid >> 5;
    const int lane = tid & 31;
    const int bg   = lane & 15;            // batch base (lanes adjacent in b -> bank-clean)
    const int jg   = lane >> 4;            // j-group of 4
    const int jbase = blockIdx.x * JPB;

    // ---- stage w slice once, transposed to [j][k] (entire kernel lifetime) ----
    for (int k = tid; k < HID; k += 256) {
        float4 a  = __ldg((const float4*)&w_hh[(size_t)k * HID + jbase]);
        float4 b4 = __ldg((const float4*)&w_hh[(size_t)k * HID + jbase + 4]);
        wsT[0 * 1026 + k] = a.x;  wsT[1 * 1026 + k] = a.y;
        wsT[2 * 1026 + k] = a.z;  wsT[3 * 1026 + k] = a.w;
        wsT[4 * 1026 + k] = b4.x; wsT[5 * 1026 + k] = b4.y;
        wsT[6 * 1026 + k] = b4.z; wsT[7 * 1026 + k] = b4.w;
    }

    // epilogue constants: thread -> outputs (b=eb, j=ej0) and (b=eb, j=ej0+4)
    const int eb  = tid & 63;
    const int ej0 = tid >> 6;              // 0..3
    const float bh0 = b_h[jbase + ej0];
    const float bh1 = b_h[jbase + ej0 + 4];

    __syncthreads();

    for (int t = 0; t < SEQ; t++) {
        const int par = t & 1;
        const float* __restrict__ hin  = g_h[par];
        float* __restrict__ hout = g_h[par ^ 1];

        ull acc[4][4];                     // [bi][ji] packed f32x2 (even/odd k partials)
        #pragma unroll
        for (int bi = 0; bi < 4; bi++)
            #pragma unroll
            for (int ji = 0; ji < 4; ji++) acc[bi][ji] = 0ull;

        float4 pf[8];
        // coalesced load of chunk: thread r-th quad: row = (tid+r*256)>>5, col4 = (tid+r*256)&31
        #define LDG_CHUNK(c) { \
            _Pragma("unroll") \
            for (int r = 0; r < 8; r++) { \
                int i = tid + r * 256; int row = i >> 5, col = i & 31; \
                pf[r] = __ldcg((const float4*)&hin[(size_t)row * HID + (c) * 128 + col * 4]); \
            } }
        // float4 XOR swizzle: conflict-free STS.128, <=2-way on strided reads
        #define STS_CHUNK(dst) { \
            _Pragma("unroll") \
            for (int r = 0; r < 8; r++) { \
                int i = tid + r * 256; int row = i >> 5, col = i & 31; \
                *(float4*)&(dst)[row * 128 + ((col ^ (row & 7)) << 2)] = pf[r]; \
            } }

        LDG_CHUNK(0); STS_CHUNK(buf0);
        __syncthreads();

        #pragma unroll 1
        for (int c = 0; c < 8; c++) {
            const float* cur = (c & 1) ? buf1 : buf0;
            if (c < 7) LDG_CHUNK(c + 1);   // prefetch into regs (L2 latency hidden)

            // warp owns k rows [warp*16, +16) of this chunk, as 8 k-pairs
            #pragma unroll
            for (int kp = 0; kp < 8; kp++) {
                const int k2  = warp * 16 + kp * 2;
                const int f4  = k2 >> 2;
                const int off = k2 & 3;
                ull hv[4], wv[4];
                #pragma unroll
                for (int bi = 0; bi < 4; bi++) {
                    int row = bg + 16 * bi;
                    hv[bi] = *(const ull*)&cur[row * 128 + ((f4 ^ (row & 7)) << 2) + off];
                }
                #pragma unroll
                for (int ji = 0; ji < 4; ji++)
                    wv[ji] = *(const ull*)&wsT[(jg * 4 + ji) * 1026 + c * 128 + k2];
                #pragma unroll
                for (int bi = 0; bi < 4; bi++)
                    #pragma unroll
                    for (int ji = 0; ji < 4; ji++)
                        ffma2(acc[bi][ji], hv[bi], wv[ji]);
            }
            __syncthreads();
            if (c < 7) {
                STS_CHUNK((c & 1) ? buf0 : buf1);
                __syncthreads();
            }
        }

        // split-k reduction: dump f32x2 partials (red aliases buf0; safe after last sync)
        #pragma unroll
        for (int bi = 0; bi < 4; bi++)
            #pragma unroll
            for (int ji = 0; ji < 4; ji++) {
                int o = (jg * 4 + ji) * 64 + bg + 16 * bi;   // o = j*64 + b
                red[warp * 512 + o] = acc[bi][ji];
            }
        __syncthreads();

        // final sum + epilogue
        float2 s0 = make_float2(0.f, 0.f), s1 = make_float2(0.f, 0.f);
        #pragma unroll
        for (int w = 0; w < 8; w++) {
            float2 v0 = *(const float2*)&red[w * 512 + tid];
            float2 v1 = *(const float2*)&red[w * 512 + tid + 256];
            s0.x += v0.x; s0.y += v0.y;
            s1.x += v1.x; s1.y += v1.y;
        }
        int xi = __ldg(&X[eb * SEQ + t]);
        const float* ex = &w_xh[(size_t)xi * HID + jbase];
        float v0 = tanhf(s0.x + s0.y + __ldg(&ex[ej0]) + bh0);
        float v1 = tanhf(s1.x + s1.y + __ldg(&ex[ej0 + 4]) + bh1);
        __stcg(&hout[eb * HID + jbase + ej0], v0);
        __stcg(&hout[eb * HID + jbase + ej0 + 4], v1);
        g_H[((size_t)t * BATCH + eb) * HID + jbase + ej0] = v0;
        g_H[((size_t)t * BATCH + eb) * HID + jbase + ej0 + 4] = v1;

        __syncthreads();   // protect red before next step's STS overwrites buf0

        // grid barrier: hout must be globally visible before next step
        if (t < SEQ - 1) {
            if (tid == 0) {
                __threadfence();
                unsigned prev = atomicAdd(&g_cnt, 1);
                if (prev == NBLK - 1) {
                    g_cnt = 0;
                    __threadfence();
                    atomicAdd(&g_gen, 1);   // release
                } else {
                    unsigned target = (unsigned)(t + 1), v;
                    do {
                        __nanosleep(32);
                        asm volatile("ld.acquire.gpu.global.u32 %0, [%1];"
                                     : "=r"(v) : "l"(&g_gen) : "memory");
                    } while (v < target);
                }
            }
            __syncthreads();
        }
        #undef LDG_CHUNK
        #undef STS_CHUNK
    }
}

// ---------------------------------------------------------------
// Big output GEMM with tf32 mma.sync:
//   Y[m, n] = sum_k H[m,k] * w_ho[k,n] + b_o[n]
// M = 16384, K = 1024, N = 8192, fp32 accumulate.
// Block tile 128x128, BK=32, 8 warps (4x2), warp tile 32x64.
// tf32 conversion done once at smem-store time.
// ---------------------------------------------------------------
__device__ __forceinline__ uint32_t f2tf32(float x) {
    uint32_t r;
    asm("cvt.rna.tf32.f32 %0, %1;" : "=r"(r) : "f"(x));
    return r;
}

__device__ __forceinline__ void mma_16n8k8(float* c, const uint32_t* a, const uint32_t* b) {
    asm volatile(
        "mma.sync.aligned.m16n8k8.row.col.f32.tf32.tf32.f32 "
        "{%0,%1,%2,%3}, {%4,%5,%6,%7}, {%8,%9}, {%0,%1,%2,%3};\n"
        : "+f"(c[0]), "+f"(c[1]), "+f"(c[2]), "+f"(c[3])
        : "r"(a[0]), "r"(a[1]), "r"(a[2]), "r"(a[3]), "r"(b[0]), "r"(b[1]));
}

__global__ __launch_bounds__(256) void k_gemm(
    const float* __restrict__ Wo, const float* __restrict__ b_o,
    float* __restrict__ Y)
{
    __shared__ uint32_t As[128][36];   // [m][k] tf32
    __shared__ uint32_t Bs[128][36];   // [n][k] tf32 (transposed tile of w_ho)

    const int m0 = blockIdx.y * 128;
    const int n0 = blockIdx.x * 128;
    const int tid = threadIdx.x;
    const int warp = tid >> 5, lane = tid & 31;
    const int wr = warp >> 1;       // 0..3  (m direction, 32 rows each)
    const int wc = warp & 1;        // 0..1  (n direction, 64 cols each)
    const int g = lane >> 2;        // groupID
    const int tg = lane & 3;        // thread in group

    float c[2][8][4];
    #pragma unroll
    for (int i = 0; i < 2; i++)
        #pragma unroll
        for (int jn = 0; jn < 8; jn++)
            #pragma unroll
            for (int q = 0; q < 4; q++) c[i][jn][q] = 0.f;

    for (int kt = 0; kt < HID; kt += 32) {
        // load A tile: 128 rows x 32 k (float4 along k), cvt once here
        #pragma unroll
        for (int r = 0; r < 4; r++) {
            int i = tid + r * 256;           // 0..1023
            int row = i >> 3;
            int c4 = (i & 7) << 2;
            float4 v = *reinterpret_cast<const float4*>(
                &g_H[((size_t)(m0 + row)) * HID + kt + c4]);
            As[row][c4 + 0] = f2tf32(v.x); As[row][c4 + 1] = f2tf32(v.y);
            As[row][c4 + 2] = f2tf32(v.z); As[row][c4 + 3] = f2tf32(v.w);
        }
        // load B tile: 32 k x 128 n (float4 along n), store transposed, cvt once
        #pragma unroll
        for (int r = 0; r < 4; r++) {
            int i = tid + r * 256;
            int k = i >> 5;                  // 0..31
            int n4 = (i & 31) << 2;          // 0..124
            float4 v = *reinterpret_cast<const float4*>(
                &Wo[((size_t)(kt + k)) * VOCAB + n0 + n4]);
            Bs[n4 + 0][k] = f2tf32(v.x); Bs[n4 + 1][k] = f2tf32(v.y);
            Bs[n4 + 2][k] = f2tf32(v.z); Bs[n4 + 3][k] = f2tf32(v.w);
        }
        __syncthreads();

        #pragma unroll
        for (int kk = 0; kk < 4; kk++) {
            uint32_t a[2][4];
            #pragma unroll
            for (int im = 0; im < 2; im++) {
                int row = wr * 32 + im * 16;
                a[im][0] = As[row + g][kk * 8 + tg];
                a[im][1] = As[row + g + 8][kk * 8 + tg];
                a[im][2] = As[row + g][kk * 8 + tg + 4];
                a[im][3] = As[row + g + 8][kk * 8 + tg + 4];
            }
            uint32_t b[8][2];
            #pragma unroll
            for (int in = 0; in < 8; in++) {
                int n = wc * 64 + in * 8 + g;
                b[in][0] = Bs[n][kk * 8 + tg];
                b[in][1] = Bs[n][kk * 8 + tg + 4];
            }
            #pragma unroll
            for (int im = 0; im < 2; im++)
                #pragma unroll
                for (int in = 0; in < 8; in++)
                    mma_16n8k8(c[im][in], a[im], b[in]);
        }
        __syncthreads();
    }

    // epilogue: add bias, write fp32 Y
    #pragma unroll
    for (int im = 0; im < 2; im++) {
        #pragma unroll
        for (int in = 0; in < 8; in++) {
            int col = n0 + wc * 64 + in * 8 + tg * 2;
            float bo0 = b_o[col], bo1 = b_o[col + 1];
            int row0 = m0 + wr * 32 + im * 16 + g;
            float2 v0 = make_float2(c[im][in][0] + bo0, c[im][in][1] + bo1);
            float2 v1 = make_float2(c[im][in][2] + bo0, c[im][in][3] + bo1);
            *reinterpret_cast<float2*>(&Y[(size_t)row0 * VOCAB + col]) = v0;
            *reinterpret_cast<float2*>(&Y[((size_t)row0 + 8) * VOCAB + col]) = v1;
        }
    }
}

__global__ void k_copy_hfinal(float* __restrict__ dst) {
    int i = blockIdx.x * blockDim.x + threadIdx.x;
    if (i < BATCH * HID) dst[i] = g_h[0][i];   // after 256 steps, final state is in parity 0
}

// ---------------------------------------------------------------
extern "C" void kernel_launch(void* const* d_in, const int* in_sizes, int n_in,
                              void* d_out, int out_size) {
    const int*   X      = (const int*)d_in[0];    // (B, S) int32
    const float* status = (const float*)d_in[1];  // (B, H)
    const float* w_xh   = (const float*)d_in[2];  // (V, H)
    const float* w_hh   = (const float*)d_in[3];  // (H, H)
    const float* w_ho   = (const float*)d_in[4];  // (H, V)
    const float* b_h    = (const float*)d_in[5];  // (H)
    const float* b_o    = (const float*)d_in[6];  // (V)
    float* out = (float*)d_out;

    const int smem_bytes = (8 * 1026 + 2 * 64 * 128) * 4;   // 98,368 B
    cudaFuncSetAttribute(k_rnn, cudaFuncAttributeMaxDynamicSharedMemorySize, smem_bytes);

    k_init<<<(BATCH * HID + 255) / 256, 256>>>(status);

    // all 256 recurrence steps in one persistent kernel
    k_rnn<<<NBLK, 256, smem_bytes>>>(X, w_xh, w_hh, b_h);

    // Y: (S*B, V) = (16384, 8192)
    k_gemm<<<dim3(VOCAB / 128, (SEQ * BATCH) / 128), 256>>>(w_ho, b_o, out);

    // h_final appended after Y if the output buffer expects it
    long long ybytes = (long long)SEQ * BATCH * VOCAB;
    if ((long long)out_size >= ybytes + (long long)BATCH * HID)
        k_copy_hfinal<<<(BATCH * HID + 255) / 256, 256>>>(out + (size_t)SEQ * BATCH * VOCAB);
}

// round 15
// speedup vs baseline: 2.4183x; 1.1771x over previous
#include <cuda_runtime.h>
#include <cuda_bf16.h>
#include <cstdint>

// Problem dims
#define VOCAB 8192
#define HID   1024
#define BATCH 64
#define SEQ   256

#define NBLK  128      // persistent blocks (1 per SM, <=148 -> co-resident)

typedef unsigned long long ull;

// -------- device scratch (static: no runtime allocation allowed) --------
__device__ __align__(16) float g_H[(size_t)SEQ * BATCH * HID];  // hidden states [t][b][j] (GEMM layout)
__device__ __align__(16) float g_h[2][HID * BATCH];             // ping-pong h TRANSPOSED: [k][b]
__device__ unsigned g_cnt;   // grid barrier arrive counter
__device__ unsigned g_gen;   // grid barrier generation

// transpose status (B,H) -> g_h[0] = hT (H,B); also reset barrier state
__global__ void k_init_t(const float* __restrict__ status) {
    __shared__ float tile[32][33];
    int j0 = blockIdx.x * 32, b0 = blockIdx.y * 32;
    int tx = threadIdx.x, ty = threadIdx.y;
    #pragma unroll
    for (int i = 0; i < 32; i += 8)
        tile[ty + i][tx] = status[(size_t)(b0 + ty + i) * HID + j0 + tx];   // coalesced over j
    __syncthreads();
    #pragma unroll
    for (int i = 0; i < 32; i += 8)
        g_h[0][(size_t)(j0 + ty + i) * BATCH + b0 + tx] = tile[tx][ty + i]; // coalesced over b
    if (blockIdx.x == 0 && blockIdx.y == 0 && tx == 0 && ty == 0) { g_cnt = 0; g_gen = 0; }
}

// packed dual fp32 FMA (sm_100+): acc = a*b + acc elementwise on f32x2
__device__ __forceinline__ void ffma2(ull& acc, ull a, ull b) {
    asm("fma.rn.f32x2 %0, %1, %2, %0;" : "+l"(acc) : "l"(a), "l"(b));
}

// cp.async 16B, L2-only (.cg) — required: h is produced by other SMs each step
__device__ __forceinline__ void cp16(uint32_t saddr, const float* g) {
    asm volatile("cp.async.cg.shared.global [%0], [%1], 16;" :: "r"(saddr), "l"(g));
}
#define CP_COMMIT() asm volatile("cp.async.commit_group;" ::: "memory")
#define CP_WAIT(N)  asm volatile("cp.async.wait_group %0;" :: "n"(N) : "memory")

// ---------------------------------------------------------------
// Persistent RNN recurrence, all 256 steps.
// Block (64 j-groups x 2 b-groups): owns j-slice of 16 (w_hh dup-
// packed in smem, 128KB, staged once) and b-slice of 32.
// Warp w owns k in [w*128, +128): streams 8 pieces of 16k x 32b
// via cp.async.cg triple-buffer (warp-private, no block syncs).
// Per step: compute (f32x2 b-pair packing), smem split-k reduce,
// epilogue (embed gather + bias + tanh), grid barrier.
// dyn smem: wdup 128KB + hbuf 48KB + red 16KB = 192KB (1 blk/SM).
// ---------------------------------------------------------------
__global__ __launch_bounds__(256, 1) void k_rnn(
    const int* __restrict__ X, const float* __restrict__ w_xh,
    const float* __restrict__ w_hh, const float* __restrict__ b_h)
{
    extern __shared__ float smem[];
    float* wdup = smem;                         // [1024][32]: (w[k][j],w[k][j]) pairs, 16 j
    float* hbuf = smem + 32768;                 // [8 warps][3 bufs][16k][32b]
    ull*   red  = (ull*)(smem + 32768 + 12288); // [8][256] f32x2 partials

    const int tid  = threadIdx.x;
    const int warp = tid >> 5;
    const int lane = tid & 31;
    const int bpg  = lane & 3;                  // 4 b-pair groups (4 bp each)
    const int jq   = lane >> 2;                 // 8 j-quads (2 j each)
    const int jbase = (blockIdx.x >> 1) * 16;
    const int bbase = (blockIdx.x & 1) * 32;
    const int ks    = warp * 128;               // warp's k-slice start

    // ---- stage w slice once, duplicated pairs [k][(j0,j0,j1,j1,...)] ----
    for (int k = tid; k < HID; k += 256) {
        const float* wr = w_hh + (size_t)k * HID + jbase;
        float* d = wdup + k * 32;
        #pragma unroll
        for (int j = 0; j < 16; j++) {
            float v = wr[j];
            *(float2*)&d[2 * j] = make_float2(v, v);
        }
    }

    float* mybuf = hbuf + warp * (3 * 512);
    uint32_t sb0 = (uint32_t)__cvta_generic_to_shared(mybuf);
    const uint32_t sbv[3] = {sb0, sb0 + 512u * 4u, sb0 + 1024u * 4u};

    // epilogue constants: thread -> (j = ej, b-pair ebp)
    const int ej  = tid >> 4;                   // 0..15
    const int ebp = tid & 15;                   // 0..15
    const int eb  = bbase + 2 * ebp;
    const float bh = b_h[jbase + ej];

    __syncthreads();

    #pragma unroll 1
    for (int t = 0; t < SEQ; t++) {
        const float* __restrict__ hin  = g_h[t & 1];        // hT [k][64]
        float* __restrict__ hout = g_h[(t & 1) ^ 1];

        // issue piece p (16k x 32b, 2KB) into buffer bi_
        #define ISSUE(p, bi_) { \
            _Pragma("unroll") \
            for (int q = 0; q < 4; q++) { \
                int i = lane + q * 32; int kl = i >> 3; int bo = (i & 7) * 4; \
                cp16(sbv[bi_] + (uint32_t)(kl * 32 + bo) * 4u, \
                     hin + (size_t)(ks + (p) * 16 + kl) * BATCH + bbase + bo); \
            } \
            CP_COMMIT(); }

        ull acc[4][2];
        #pragma unroll
        for (int bi = 0; bi < 4; bi++) { acc[bi][0] = 0ull; acc[bi][1] = 0ull; }

        ISSUE(0, 0); ISSUE(1, 1); ISSUE(2, 2);

        // compute piece c from buffer c%3 (data k = ks + c*16 ..)
        #define PIECE(c, NW) { \
            CP_WAIT(NW); __syncwarp(); \
            const float* hb = mybuf + ((c) % 3) * 512; \
            const float* wp = wdup + (size_t)(ks + (c) * 16) * 32; \
            _Pragma("unroll") \
            for (int kl = 0; kl < 16; kl++) { \
                ulonglong2 wv = *(const ulonglong2*)(wp + kl * 32 + jq * 4); \
                _Pragma("unroll") \
                for (int bi = 0; bi < 4; bi++) { \
                    ull hv = *(const ull*)(hb + kl * 32 + bpg * 8 + bi * 2); \
                    ffma2(acc[bi][0], hv, wv.x); \
                    ffma2(acc[bi][1], hv, wv.y); \
                } \
            } \
            __syncwarp(); }

        PIECE(0, 2); ISSUE(3, 0);
        PIECE(1, 2); ISSUE(4, 1);
        PIECE(2, 2); ISSUE(5, 2);
        PIECE(3, 2); ISSUE(6, 0);
        PIECE(4, 2); ISSUE(7, 1);
        PIECE(5, 2);
        PIECE(6, 1);
        PIECE(7, 0);

        // ---- split-k partial dump: o = j*16 + bp (f32x2 over b-pair) ----
        #pragma unroll
        for (int jj = 0; jj < 2; jj++) {
            int o2 = (jq * 2 + jj) * 16 + bpg * 4;
            ulonglong2 v01; v01.x = acc[0][jj]; v01.y = acc[1][jj];
            ulonglong2 v23; v23.x = acc[2][jj]; v23.y = acc[3][jj];
            *(ulonglong2*)&red[warp * 256 + o2]     = v01;
            *(ulonglong2*)&red[warp * 256 + o2 + 2] = v23;
        }
        __syncthreads();

        // ---- final reduce + epilogue ----
        float2 s = make_float2(0.f, 0.f);
        #pragma unroll
        for (int w = 0; w < 8; w++) {
            float2 v = *(const float2*)&red[w * 256 + tid];
            s.x += v.x; s.y += v.y;
        }
        int xi0 = __ldg(&X[eb * SEQ + t]);
        int xi1 = __ldg(&X[(eb + 1) * SEQ + t]);
        float e0 = __ldg(&w_xh[(size_t)xi0 * HID + jbase + ej]);
        float e1 = __ldg(&w_xh[(size_t)xi1 * HID + jbase + ej]);
        float v0 = tanhf(s.x + e0 + bh);
        float v1 = tanhf(s.y + e1 + bh);
        __stcg((float2*)&hout[(size_t)(jbase + ej) * BATCH + eb], make_float2(v0, v1));
        g_H[((size_t)t * BATCH + eb) * HID + jbase + ej]     = v0;
        g_H[((size_t)t * BATCH + eb + 1) * HID + jbase + ej] = v1;

        __syncthreads();   // all hout stores issued + red consumed before barrier/next step

        // ---- grid barrier: hout must be globally visible before next step ----
        if (t < SEQ - 1) {
            if (tid == 0) {
                __threadfence();
                unsigned prev = atomicAdd(&g_cnt, 1);
                if (prev == NBLK - 1) {
                    g_cnt = 0;
                    __threadfence();
                    atomicAdd(&g_gen, 1);   // release
                } else {
                    unsigned target = (unsigned)(t + 1), v;
                    do {
                        __nanosleep(32);
                        asm volatile("ld.acquire.gpu.global.u32 %0, [%1];"
                                     : "=r"(v) : "l"(&g_gen) : "memory");
                    } while (v < target);
                }
            }
            __syncthreads();
        }
        #undef ISSUE
        #undef PIECE
    }
}

// ---------------------------------------------------------------
// Big output GEMM with tf32 mma.sync:
//   Y[m, n] = sum_k H[m,k] * w_ho[k,n] + b_o[n]
// M = 16384, K = 1024, N = 8192, fp32 accumulate.
// Block tile 128x128, BK=32, 8 warps (4x2), warp tile 32x64.
// tf32 conversion done once at smem-store time.
// ---------------------------------------------------------------
__device__ __forceinline__ uint32_t f2tf32(float x) {
    uint32_t r;
    asm("cvt.rna.tf32.f32 %0, %1;" : "=r"(r) : "f"(x));
    return r;
}

__device__ __forceinline__ void mma_16n8k8(float* c, const uint32_t* a, const uint32_t* b) {
    asm volatile(
        "mma.sync.aligned.m16n8k8.row.col.f32.tf32.tf32.f32 "
        "{%0,%1,%2,%3}, {%4,%5,%6,%7}, {%8,%9}, {%0,%1,%2,%3};\n"
        : "+f"(c[0]), "+f"(c[1]), "+f"(c[2]), "+f"(c[3])
        : "r"(a[0]), "r"(a[1]), "r"(a[2]), "r"(a[3]), "r"(b[0]), "r"(b[1]));
}

__global__ __launch_bounds__(256) void k_gemm(
    const float* __restrict__ Wo, const float* __restrict__ b_o,
    float* __restrict__ Y)
{
    __shared__ uint32_t As[128][36];   // [m][k] tf32
    __shared__ uint32_t Bs[128][36];   // [n][k] tf32 (transposed tile of w_ho)

    const int m0 = blockIdx.y * 128;
    const int n0 = blockIdx.x * 128;
    const int tid = threadIdx.x;
    const int warp = tid >> 5, lane = tid & 31;
    const int wr = warp >> 1;       // 0..3  (m direction, 32 rows each)
    const int wc = warp & 1;        // 0..1  (n direction, 64 cols each)
    const int g = lane >> 2;        // groupID
    const int tg = lane & 3;        // thread in group

    float c[2][8][4];
    #pragma unroll
    for (int i = 0; i < 2; i++)
        #pragma unroll
        for (int jn = 0; jn < 8; jn++)
            #pragma unroll
            for (int q = 0; q < 4; q++) c[i][jn][q] = 0.f;

    for (int kt = 0; kt < HID; kt += 32) {
        // load A tile: 128 rows x 32 k (float4 along k), cvt once here
        #pragma unroll
        for (int r = 0; r < 4; r++) {
            int i = tid + r * 256;           // 0..1023
            int row = i >> 3;
            int c4 = (i & 7) << 2;
            float4 v = *reinterpret_cast<const float4*>(
                &g_H[((size_t)(m0 + row)) * HID + kt + c4]);
            As[row][c4 + 0] = f2tf32(v.x); As[row][c4 + 1] = f2tf32(v.y);
            As[row][c4 + 2] = f2tf32(v.z); As[row][c4 + 3] = f2tf32(v.w);
        }
        // load B tile: 32 k x 128 n (float4 along n), store transposed, cvt once
        #pragma unroll
        for (int r = 0; r < 4; r++) {
            int i = tid + r * 256;
            int k = i >> 5;                  // 0..31
            int n4 = (i & 31) << 2;          // 0..124
            float4 v = *reinterpret_cast<const float4*>(
                &Wo[((size_t)(kt + k)) * VOCAB + n0 + n4]);
            Bs[n4 + 0][k] = f2tf32(v.x); Bs[n4 + 1][k] = f2tf32(v.y);
            Bs[n4 + 2][k] = f2tf32(v.z); Bs[n4 + 3][k] = f2tf32(v.w);
        }
        __syncthreads();

        #pragma unroll
        for (int kk = 0; kk < 4; kk++) {
            uint32_t a[2][4];
            #pragma unroll
            for (int im = 0; im < 2; im++) {
                int row = wr * 32 + im * 16;
                a[im][0] = As[row + g][kk * 8 + tg];
                a[im][1] = As[row + g + 8][kk * 8 + tg];
                a[im][2] = As[row + g][kk * 8 + tg + 4];
                a[im][3] = As[row + g + 8][kk * 8 + tg + 4];
            }
            uint32_t b[8][2];
            #pragma unroll
            for (int in = 0; in < 8; in++) {
                int n = wc * 64 + in * 8 + g;
                b[in][0] = Bs[n][kk * 8 + tg];
                b[in][1] = Bs[n][kk * 8 + tg + 4];
            }
            #pragma unroll
            for (int im = 0; im < 2; im++)
                #pragma unroll
                for (int in = 0; in < 8; in++)
                    mma_16n8k8(c[im][in], a[im], b[in]);
        }
        __syncthreads();
    }

    // epilogue: add bias, write fp32 Y
    #pragma unroll
    for (int im = 0; im < 2; im++) {
        #pragma unroll
        for (int in = 0; in < 8; in++) {
            int col = n0 + wc * 64 + in * 8 + tg * 2;
            float bo0 = b_o[col], bo1 = b_o[col + 1];
            int row0 = m0 + wr * 32 + im * 16 + g;
            float2 v0 = make_float2(c[im][in][0] + bo0, c[im][in][1] + bo1);
            float2 v1 = make_float2(c[im][in][2] + bo0, c[im][in][3] + bo1);
            *reinterpret_cast<float2*>(&Y[(size_t)row0 * VOCAB + col]) = v0;
            *reinterpret_cast<float2*>(&Y[((size_t)row0 + 8) * VOCAB + col]) = v1;
        }
    }
}

// de-transpose final hidden state: dst[b][j] = g_h[0][j][b]
__global__ void k_hfinal_t(float* __restrict__ dst) {
    __shared__ float tile[32][33];
    int j0 = blockIdx.x * 32, b0 = blockIdx.y * 32;
    int tx = threadIdx.x, ty = threadIdx.y;
    #pragma unroll
    for (int i = 0; i < 32; i += 8)
        tile[ty + i][tx] = g_h[0][(size_t)(j0 + ty + i) * BATCH + b0 + tx];  // coalesced over b
    __syncthreads();
    #pragma unroll
    for (int i = 0; i < 32; i += 8)
        dst[(size_t)(b0 + ty + i) * HID + j0 + tx] = tile[tx][ty + i];       // coalesced over j
}

// ---------------------------------------------------------------
extern "C" void kernel_launch(void* const* d_in, const int* in_sizes, int n_in,
                              void* d_out, int out_size) {
    const int*   X      = (const int*)d_in[0];    // (B, S) int32
    const float* status = (const float*)d_in[1];  // (B, H)
    const float* w_xh   = (const float*)d_in[2];  // (V, H)
    const float* w_hh   = (const float*)d_in[3];  // (H, H)
    const float* w_ho   = (const float*)d_in[4];  // (H, V)
    const float* b_h    = (const float*)d_in[5];  // (H)
    const float* b_o    = (const float*)d_in[6];  // (V)
    float* out = (float*)d_out;

    const int smem_bytes = (32768 + 12288 + 4096) * 4;   // 196,608 B (192 KB)
    cudaFuncSetAttribute(k_rnn, cudaFuncAttributeMaxDynamicSharedMemorySize, smem_bytes);

    k_init_t<<<dim3(HID / 32, BATCH / 32), dim3(32, 8)>>>(status);

    // all 256 recurrence steps in one persistent kernel
    k_rnn<<<NBLK, 256, smem_bytes>>>(X, w_xh, w_hh, b_h);

    // Y: (S*B, V) = (16384, 8192)
    k_gemm<<<dim3(VOCAB / 128, (SEQ * BATCH) / 128), 256>>>(w_ho, b_o, out);

    // h_final appended after Y if the output buffer expects it
    long long ybytes = (long long)SEQ * BATCH * VOCAB;
    if ((long long)out_size >= ybytes + (long long)BATCH * HID)
        k_hfinal_t<<<dim3(HID / 32, BATCH / 32), dim3(32, 8)>>>(out + (size_t)SEQ * BATCH * VOCAB);
}